// round 11
// baseline (speedup 1.0000x reference)
#include <cuda_runtime.h>
#include <cuda_bf16.h>

#define BS    4
#define NH    8
#define SEQ   2048
#define DK    64
#define NP    129
#define TI    4          // i-rows per block
#define PSTR2 130        // float2 stride for swT rows
#define NT    256

// table layout (aliased over swT+sq after proj):
//   t[il][hp][p][2]  hp = head pair, p padded to 132
#define HPSTR  264                       // floats per head-pair (132 * 2)
#define TBL_IL (4 * HPSTR)               // 1056 floats per i-row
#define SWT_BYTES (32 * PSTR2 * 8)       // 33280
#define SQ_BYTES  (TI * NH * DK * 4)     // 8192
#define TBL_BYTES (TI * TBL_IL * 4)      // 16896
#define SMEM_BYTES (SWT_BYTES + SQ_BYTES) // 41472  (> TBL_BYTES, aliased)

typedef unsigned long long ull;

__device__ __forceinline__ ull fma2(ull a, ull b, ull c) {
    ull d;
    asm("fma.rn.f32x2 %0, %1, %2, %3;" : "=l"(d) : "l"(a), "l"(b), "l"(c));
    return d;
}

__global__ void __launch_bounds__(NT, 4)
fused_kernel(const float* __restrict__ q,
             const int*   __restrict__ dist,
             const float* __restrict__ w,
             float*       __restrict__ out) {
    extern __shared__ char smem_raw[];
    float2* swT = reinterpret_cast<float2*>(smem_raw);                 // [32][PSTR2]
    float*  sq  = reinterpret_cast<float*>(smem_raw + SWT_BYTES);      // [TI][NH][DK]
    float*  tsm = reinterpret_cast<float*>(smem_raw);                  // aliased table

    const int tid = threadIdx.x;
    const int bi  = blockIdx.x;              // 0..2047
    const int b   = bi >> 9;                 // 512 blocks per batch
    const int i0  = (bi & 511) * TI;

    // ---- load w transposed: swT[k2][p]; pad p>=129 with 0
    {
        const float2* w2 = reinterpret_cast<const float2*>(w);
        for (int idx = tid; idx < 32 * PSTR2; idx += NT) {
            const int k2 = idx / PSTR2;
            const int p  = idx - k2 * PSTR2;
            float2 v = make_float2(0.f, 0.f);
            if (p < NP) v = w2[p * 32 + k2];
            swT[idx] = v;
        }
    }
    // ---- load q tile: sq[r][h][k]  (512 float4)
    {
        const float4* q4 = reinterpret_cast<const float4*>(q);
        float4* sq4 = reinterpret_cast<float4*>(sq);
        for (int idx = tid; idx < TI * NH * 16; idx += NT) {
            const int r  = idx >> 7;
            const int h  = (idx >> 4) & 7;
            const int kq = idx & 15;
            sq4[idx] = q4[(((size_t)(b * NH + h) * SEQ) + i0 + r) * 16 + kq];
        }
    }
    __syncthreads();

    // ---- projection: 8 warps = 4 rows x 2 p-halves; 8 heads per warp
    const int wid = tid >> 5, lane = tid & 31;
    {
        const int r  = wid >> 1;
        const int ph = wid & 1;
        const int p0 = lane + ph * 32;           // and p0 + 64
        const float2* sqf2 = reinterpret_cast<const float2*>(sq) + r * (NH * 32);

        ull acc[NH][2];
#pragma unroll
        for (int h = 0; h < NH; h++) { acc[h][0] = 0ULL; acc[h][1] = 0ULL; }

#pragma unroll 8
        for (int k2 = 0; k2 < 32; k2++) {
            const float2* wrow = swT + k2 * PSTR2;
            const ull wv0 = *reinterpret_cast<const ull*>(wrow + p0);
            const ull wv1 = *reinterpret_cast<const ull*>(wrow + p0 + 64);
#pragma unroll
            for (int h = 0; h < NH; h++) {
                const ull qv = *reinterpret_cast<const ull*>(sqf2 + h * 32 + k2);
                acc[h][0] = fma2(qv, wv0, acc[h][0]);
                acc[h][1] = fma2(qv, wv1, acc[h][1]);
            }
        }

        // p = 128 epilogue values (computed BEFORE aliasing sync)
        float veps[4];
        {
            const float2 wq = swT[lane * PSTR2 + 128];
#pragma unroll
            for (int j = 0; j < 4; j++) {
                const int pr = wid * 4 + j;          // 0..31 = (rr,hh)
                const int rr = pr >> 3, hh = pr & 7;
                const float2 qq = *(reinterpret_cast<const float2*>(sq) +
                                    (rr * NH + hh) * 32 + lane);
                float v = qq.x * wq.x + qq.y * wq.y;
#pragma unroll
                for (int o = 16; o > 0; o >>= 1)
                    v += __shfl_xor_sync(0xffffffffu, v, o);
                veps[j] = v;
            }
        }

        __syncthreads();   // everyone done reading swT/sq -> safe to alias

        // write table t[r][hp][p][2]
        float* tb = tsm + r * TBL_IL;
#pragma unroll
        for (int h = 0; h < NH; h++) {
            float* dst = tb + (h >> 1) * HPSTR + (h & 1);
            float2 v0 = *reinterpret_cast<float2*>(&acc[h][0]);
            float2 v1 = *reinterpret_cast<float2*>(&acc[h][1]);
            dst[p0 * 2]        = v0.x + v0.y;
            dst[(p0 + 64) * 2] = v1.x + v1.y;
        }
        if (lane == 0) {
#pragma unroll
            for (int j = 0; j < 4; j++) {
                const int pr = wid * 4 + j;
                const int rr = pr >> 3, hh = pr & 7;
                tsm[rr * TBL_IL + (hh >> 1) * HPSTR + 256 + (hh & 1)] = veps[j];
            }
        }
    }
    __syncthreads();

    // ---- gather: out[b,h,i,j] = t[il][h>>1][min(dist,128)][h&1]
    {
        const int4* dist4 = reinterpret_cast<const int4*>(
            dist + ((size_t)(b * SEQ + i0)) * SEQ);
        float4* out4 = reinterpret_cast<float4*>(
            out + ((size_t)b * NH * SEQ + i0) * SEQ);
        const size_t HS4 = (size_t)SEQ * (SEQ / 4);     // h stride in float4

        // flatten (il,rep) -> u = 0..7 ; jv = (u&1)*256 + tid ; il = u>>1
        int4 dcur = __ldcs(&dist4[tid]);
#pragma unroll
        for (int u = 0; u < 2 * TI; u++) {
            int4 dnxt;
            if (u + 1 < 2 * TI)
                dnxt = __ldcs(&dist4[((u + 1) >> 1) * 512 + ((u + 1) & 1) * 256 + tid]);

            const int il = u >> 1;
            const int jv = (u & 1) * 256 + tid;
            const int pa = min(dcur.x, 128);
            const int pb = min(dcur.y, 128);
            const int pc = min(dcur.z, 128);
            const int pd = min(dcur.w, 128);

            const float* tb = tsm + il * TBL_IL;
            float2 lp[4][4];
#pragma unroll
            for (int hp = 0; hp < 4; hp++) {
                const float2* tph = reinterpret_cast<const float2*>(tb + hp * HPSTR);
                lp[hp][0] = tph[pa];
                lp[hp][1] = tph[pb];
                lp[hp][2] = tph[pc];
                lp[hp][3] = tph[pd];
            }

            const size_t ob = (size_t)il * 512 + jv;
#pragma unroll
            for (int h = 0; h < NH; h++) {
                const int hp = h >> 1;
                float4 v;
                if ((h & 1) == 0)
                    v = make_float4(lp[hp][0].x, lp[hp][1].x, lp[hp][2].x, lp[hp][3].x);
                else
                    v = make_float4(lp[hp][0].y, lp[hp][1].y, lp[hp][2].y, lp[hp][3].y);
                __stcs(&out4[ob + h * HS4], v);
            }
            dcur = dnxt;
        }
    }
}

extern "C" void kernel_launch(void* const* d_in, const int* in_sizes, int n_in,
                              void* d_out, int out_size) {
    const float* q    = (const float*)d_in[0];
    const int*   dist = (const int*)  d_in[1];
    const float* w    = (const float*)d_in[2];
    float*       out  = (float*)d_out;

    cudaFuncSetAttribute(fused_kernel,
                         cudaFuncAttributeMaxDynamicSharedMemorySize, SMEM_BYTES);

    fused_kernel<<<BS * (SEQ / TI), NT, SMEM_BYTES>>>(q, dist, w, out);
}

// round 13
// speedup vs baseline: 1.1468x; 1.1468x over previous
#include <cuda_runtime.h>
#include <cuda_bf16.h>

#define BS    4
#define NH    8
#define SEQ   2048
#define DK    64
#define NP    129
#define TI    4          // i-rows per block == warps per block
#define PSTR2 130        // float2 stride for swT rows
#define TSTR  132        // float stride per head in per-warp table
#define NT    128

#define TBL_WARP (NH * TSTR)                 // 1056 floats per warp (4224 B)
#define SWT_BYTES (32 * PSTR2 * 8)           // 33280
#define SMEM_BYTES (SWT_BYTES + TI * TBL_WARP * 4)   // 50176

typedef unsigned long long ull;

__device__ __forceinline__ ull fma2(ull a, ull b, ull c) {
    ull d;
    asm("fma.rn.f32x2 %0, %1, %2, %3;" : "=l"(d) : "l"(a), "l"(b), "l"(c));
    return d;
}

__global__ void __launch_bounds__(NT, 4)
fused_kernel(const float* __restrict__ q,
             const int*   __restrict__ dist,
             const float* __restrict__ w,
             float*       __restrict__ out) {
    extern __shared__ char smem_raw[];
    float2* swT = reinterpret_cast<float2*>(smem_raw);                 // [32][PSTR2]
    float*  tblz = reinterpret_cast<float*>(smem_raw + SWT_BYTES);     // [TI][TBL_WARP]

    const int tid  = threadIdx.x;
    const int warp = tid >> 5;
    const int lane = tid & 31;
    const int bi   = blockIdx.x;             // 0..2047
    const int b    = bi >> 9;                // 512 blocks per batch
    const int i    = (bi & 511) * TI + warp; // this warp's row

    // ---- cooperative: load w transposed swT[k2][p]; pad p>=129 with 0
    {
        const float2* w2 = reinterpret_cast<const float2*>(w);
        for (int idx = tid; idx < 32 * PSTR2; idx += NT) {
            const int k2 = idx / PSTR2;
            const int p  = idx - k2 * PSTR2;
            float2 v = make_float2(0.f, 0.f);
            if (p < NP) v = w2[p * 32 + k2];
            swT[idx] = v;
        }
    }
    __syncthreads();   // the ONLY block-wide barrier

    float* tb = tblz + warp * TBL_WARP;            // this warp's private patch

    // ---- stage this warp's q row into the (currently dead) table patch:
    //      qsm[h*32 + k2] = (q[h][2k2], q[h][2k2+1])
    {
        float2* qsm = reinterpret_cast<float2*>(tb);
        const float2* qbase = reinterpret_cast<const float2*>(
            q + ((size_t)(b * NH) * SEQ + i) * DK);
        const size_t hstep = (size_t)SEQ * 32;      // head stride in float2
#pragma unroll
        for (int h = 0; h < NH; h++)
            qsm[h * 32 + lane] = qbase[h * hstep + lane];
    }
    __syncwarp();

    // ---- projection: this warp computes t[h][p] for all 8 h, 129 p
    {
        const float2* qsm = reinterpret_cast<const float2*>(tb);

        ull acc[NH][4];
#pragma unroll
        for (int h = 0; h < NH; h++)
#pragma unroll
            for (int u = 0; u < 4; u++) acc[h][u] = 0ULL;

#pragma unroll 4
        for (int k2 = 0; k2 < 32; k2++) {
            const float2* wrow = swT + k2 * PSTR2;
            ull wv[4];
#pragma unroll
            for (int u = 0; u < 4; u++)
                wv[u] = *reinterpret_cast<const ull*>(wrow + lane + 32 * u);
#pragma unroll
            for (int h = 0; h < NH; h++) {
                const ull qv = *reinterpret_cast<const ull*>(qsm + h * 32 + k2);
#pragma unroll
                for (int u = 0; u < 4; u++)
                    acc[h][u] = fma2(qv, wv[u], acc[h][u]);
            }
        }

        // p=128 epilogue: lane==k2; reduce across lanes for each h
        float veps[NH];
        {
            const float2 wq = swT[lane * PSTR2 + 128];
#pragma unroll
            for (int h = 0; h < NH; h++) {
                const float2 qq = qsm[h * 32 + lane];
                float v = qq.x * wq.x + qq.y * wq.y;
#pragma unroll
                for (int o = 16; o > 0; o >>= 1)
                    v += __shfl_xor_sync(0xffffffffu, v, o);
                veps[h] = v;
            }
        }
        __syncwarp();      // all lanes done reading qsm; overwrite with table

#pragma unroll
        for (int h = 0; h < NH; h++) {
            float* trow = tb + h * TSTR;
#pragma unroll
            for (int u = 0; u < 4; u++) {
                float2 v = *reinterpret_cast<float2*>(&acc[h][u]);
                trow[lane + 32 * u] = v.x + v.y;
            }
            if (lane == 0) trow[128] = veps[h];
        }
    }
    __syncwarp();

    // ---- gather: out[b,h,i,j] = tb[h][min(dist[b,i,j],128)]
    {
        const int4* drow = reinterpret_cast<const int4*>(
            dist + ((size_t)(b * SEQ + i)) * SEQ);
        float4* out4 = reinterpret_cast<float4*>(out);
        const size_t o0  = ((size_t)(b * NH) * SEQ + i) * (SEQ / 4);
        const size_t HS4 = (size_t)SEQ * (SEQ / 4);

        int4 dv[4];
#pragma unroll
        for (int it = 0; it < 4; it++)
            dv[it] = __ldcs(&drow[it * 32 + lane]);

#pragma unroll
        for (int it = 0; it < 16; it++) {
            const int4 d = dv[it & 3];
            if (it + 4 < 16)
                dv[it & 3] = __ldcs(&drow[(it + 4) * 32 + lane]);

            const int pa = min(d.x, 128);
            const int pb = min(d.y, 128);
            const int pc = min(d.z, 128);
            const int pd = min(d.w, 128);
            const size_t ob = o0 + it * 32 + lane;
#pragma unroll
            for (int h = 0; h < NH; h++) {
                const float* th = tb + h * TSTR;
                float4 v = make_float4(th[pa], th[pb], th[pc], th[pd]);
                __stcs(&out4[ob + h * HS4], v);
            }
        }
    }
}

extern "C" void kernel_launch(void* const* d_in, const int* in_sizes, int n_in,
                              void* d_out, int out_size) {
    const float* q    = (const float*)d_in[0];
    const int*   dist = (const int*)  d_in[1];
    const float* w    = (const float*)d_in[2];
    float*       out  = (float*)d_out;

    cudaFuncSetAttribute(fused_kernel,
                         cudaFuncAttributeMaxDynamicSharedMemorySize, SMEM_BYTES);

    fused_kernel<<<BS * (SEQ / TI), NT, SMEM_BYTES>>>(q, dist, w, out);
}